// round 11
// baseline (speedup 1.0000x reference)
#include <cuda_runtime.h>
#include <cstdint>

// Problem constants
#define BB 256
#define TT 512
#define NN 128

// ---------------- device scratch ----------------
__device__ float g_E[NN * NN];                 // exp(trans)
__device__ float g_lognorm[BB];
__device__ unsigned char g_bp[(size_t)BB * TT * NN]; // backpointers, 16.7 MB
__device__ int   g_lasttag[BB];

__device__ __forceinline__ unsigned ordf(float f) {
    unsigned u = __float_as_uint(f);
    return u ^ (((int)u >> 31) | 0x80000000u);
}

__device__ __forceinline__ void ffma2(unsigned long long& d,
                                      unsigned long long a,
                                      unsigned long long b) {
    asm("fma.rn.f32x2 %0, %1, %2, %0;" : "+l"(d) : "l"(a), "l"(b));
}

__device__ __forceinline__ unsigned long long add2(unsigned long long a,
                                                   unsigned long long b) {
    unsigned long long d;
    asm("add.rn.f32x2 %0, %1, %2;" : "=l"(d) : "l"(a), "l"(b));
    return d;
}

__device__ __forceinline__ float lo32(unsigned long long v) {
    return __uint_as_float((unsigned)v);
}
__device__ __forceinline__ float hi32(unsigned long long v) {
    return __uint_as_float((unsigned)(v >> 32));
}

// ---------------- K0: prep -----------------------------------------
__global__ void k_prep(const float* __restrict__ trans, float* __restrict__ out_trans) {
    int idx = blockIdx.x * 256 + threadIdx.x;
    if (idx < NN * NN) {
        float v = trans[idx];
        g_E[idx] = __expf(v);
        out_trans[idx] = v;
    }
}

// ---------------- K1: fused recurrences ------------------------------
// grid = 256, 256 threads. blockIdx&1: 0 = forward, 1 = viterbi (parity
// split — empirically fastest placement, R7/R10).
// Thread (h = tid>>7, j = tid&127): candidate-half h of column j, both
// batches in the compute phase; combine phase: batch h, column j.
// 2 syncs/step; matrix half-column in 64 regs; 4 warps/SMSP at occ 2.
__global__ __launch_bounds__(256, 2) void k_recur(const float* __restrict__ emis,
                                                  const int* __restrict__ mask,
                                                  const float* __restrict__ trans) {
    extern __shared__ float transS[];   // 64KB, viterbi blocks only (row-major)

    const int tid = threadIdx.x;
    const int h = tid >> 7;
    const int j = tid & 127;
    const int type = blockIdx.x & 1;
    const int p = blockIdx.x >> 1;
    const int b0 = 2 * p;
    const int b1 = b0 + 1;

    __shared__ __align__(16) float buf[2][2][NN];   // [sel][batch][state]
    __shared__ __align__(16) float pm[2][2][NN];    // partials [batch][half][col]
    __shared__ int pidx[2][2][NN];                  // partial argmax (viterbi)
    __shared__ float csm[2][2];                     // [sel][batch] centers (fwd)
    __shared__ unsigned char vmk[2][TT];

    // this thread's combine-batch emissions
    const float* eH = emis + (size_t)(h ? b1 : b0) * TT * NN;

    for (int i = tid; i < TT; i += 256) {
        vmk[0][i] = (unsigned char)mask[(size_t)b0 * TT + i];
        vmk[1][i] = (unsigned char)mask[(size_t)b1 * TT + i];
    }

    if (type == 0) {
        // ============ forward: alpha'_j = log(sum_i p_i E_ij) + c + emit
        unsigned long long E2[32];   // E[h*64+2k..+1][j] packed
        {
            const float* Ej = g_E + (size_t)(h * 64) * NN + j;
            #pragma unroll
            for (int k = 0; k < 32; k++) {
                unsigned lo = __float_as_uint(Ej[(size_t)(2 * k) * NN]);
                unsigned hi = __float_as_uint(Ej[(size_t)(2 * k + 1) * NN]);
                E2[k] = (unsigned long long)lo | ((unsigned long long)hi << 32);
            }
        }

        float a = eH[j];
        float c = eH[0];
        buf[0][h][j] = __expf(a - c);
        if (j == 0) csm[0][h] = a;
        float en = eH[NN + j];
        int sel = 0;
        __syncthreads();

        for (int t = 1; t < TT; t++) {
            // partial dots over candidate-half h, both batches
            unsigned long long acc0[2] = {0ull, 0ull};
            unsigned long long acc1[2] = {0ull, 0ull};
            const ulonglong2* p0 = (const ulonglong2*)(buf[sel][0] + h * 64);
            const ulonglong2* p1 = (const ulonglong2*)(buf[sel][1] + h * 64);
            #pragma unroll
            for (int k = 0; k < 16; k++) {
                ulonglong2 v0 = p0[k];
                ulonglong2 v1 = p1[k];
                ffma2(acc0[0], v0.x, E2[2 * k]);
                ffma2(acc0[1], v0.y, E2[2 * k + 1]);
                ffma2(acc1[0], v1.x, E2[2 * k]);
                ffma2(acc1[1], v1.y, E2[2 * k + 1]);
            }
            pm[0][h][j] = (lo32(acc0[0]) + hi32(acc0[0])) +
                          (lo32(acc0[1]) + hi32(acc0[1]));
            pm[1][h][j] = (lo32(acc1[0]) + hi32(acc1[0])) +
                          (lo32(acc1[1]) + hi32(acc1[1]));
            __syncthreads();

            // combine for batch h
            float s = pm[h][0][j] + pm[h][1][j];
            float cn = csm[sel][h];            // alpha_{t-1}[0]
            float ec = en;
            if (t + 1 < TT) en = eH[(size_t)(t + 1) * NN + j];
            float anew = __logf(s) + c + ec;
            a = vmk[h][t] ? anew : a;
            buf[sel ^ 1][h][j] = __expf(a - cn);
            if (j == 0) csm[sel ^ 1][h] = a;
            c = cn;
            sel ^= 1;
            __syncthreads();
        }

        // publish final centers, then logsumexp per batch
        if (j == 0) csm[0][h] = c;
        __syncthreads();
        if (tid < 64) {
            int q = tid >> 5, l = tid & 31;
            float4 v = ((const float4*)buf[sel][q])[l];
            float ts = (v.x + v.y) + (v.z + v.w);
            #pragma unroll
            for (int o = 16; o; o >>= 1) ts += __shfl_xor_sync(0xffffffffu, ts, o);
            if (l == 0) g_lognorm[q ? b1 : b0] = __logf(ts) + csm[0][q];
        }
    } else {
        // ============ viterbi: alpha'_j = max_i(a_i + T_ij) + emit, w/ bp
        unsigned long long T2[32];   // T[h*64+2k..+1][j] packed
        {
            const float* Tj = trans + (size_t)(h * 64) * NN + j;
            #pragma unroll
            for (int k = 0; k < 32; k++) {
                unsigned lo = __float_as_uint(Tj[(size_t)(2 * k) * NN]);
                unsigned hi = __float_as_uint(Tj[(size_t)(2 * k + 1) * NN]);
                T2[k] = (unsigned long long)lo | ((unsigned long long)hi << 32);
            }
        }
        // row-major trans copy for the rescan
        for (int idx = tid; idx < NN * NN / 4; idx += 256)
            ((float4*)transS)[idx] = ((const float4*)trans)[idx];

        unsigned char* bpH = g_bp + (size_t)(h ? b1 : b0) * TT * NN;
        float a = eH[j];
        buf[0][h][j] = a;
        float en = eH[NN + j];
        int sel = 0;
        const float NEGINF = -3.402823466e38f;
        __syncthreads();

        for (int t = 1; t < TT; t++) {
            // tournament over candidate-half h, both batches
            #pragma unroll
            for (int q = 0; q < 2; q++) {
                float m[4] = {NEGINF, NEGINF, NEGINF, NEGINF};
                const ulonglong2* pv = (const ulonglong2*)(buf[sel][q] + h * 64);
                #pragma unroll
                for (int k = 0; k < 16; k++) {   // cands h*64+4k.., group k>>2
                    ulonglong2 v = pv[k];
                    unsigned long long w0 = add2(v.x, T2[2 * k]);
                    unsigned long long w1 = add2(v.y, T2[2 * k + 1]);
                    const int g = k >> 2;
                    m[g] = fmaxf(m[g], lo32(w0));
                    m[g] = fmaxf(m[g], hi32(w0));
                    m[g] = fmaxf(m[g], lo32(w1));
                    m[g] = fmaxf(m[g], hi32(w1));
                }
                float bm = fmaxf(fmaxf(m[0], m[1]), fmaxf(m[2], m[3]));
                int g = 3;
                #pragma unroll
                for (int qq = 2; qq >= 0; qq--) g = (m[qq] == bm) ? qq : g;
                // rescan winning group: first index attaining bm
                const int base = h * 64 + 16 * g;
                const float* al = buf[sel][q] + base;
                const float* ts = transS + (size_t)base * NN + j;
                int u = 15;
                #pragma unroll
                for (int r = 15; r >= 0; r--) {
                    float cv = al[r] + ts[(size_t)r * NN];
                    u = (cv == bm) ? r : u;
                }
                pm[q][h][j] = bm;
                pidx[q][h][j] = base + u;
            }
            __syncthreads();

            // combine for batch h (tie -> lower half = smaller index)
            float bmA = pm[h][0][j], bmB = pm[h][1][j];
            float bm = fmaxf(bmA, bmB);
            int idx = (bmA >= bmB) ? pidx[h][0][j] : pidx[h][1][j];
            float ec = en;
            if (t + 1 < TT) en = eH[(size_t)(t + 1) * NN + j];
            int mk = vmk[h][t];
            float anew = bm + ec;
            a = mk ? anew : a;
            int bidx = mk ? idx : j;
            bpH[(size_t)t * NN + j] = (unsigned char)bidx;
            buf[sel ^ 1][h][j] = a;
            sel ^= 1;
            __syncthreads();
        }

        // last_tag per batch: warp 0 -> b0, warp 1 -> b1 (first argmax)
        if (tid < 64) {
            int q = tid >> 5, l = tid & 31;
            float4 v = ((const float4*)buf[sel][q])[l];
            float best = v.x; int bi = 4 * l;
            if (v.y > best) { best = v.y; bi = 4 * l + 1; }
            if (v.z > best) { best = v.z; bi = 4 * l + 2; }
            if (v.w > best) { best = v.w; bi = 4 * l + 3; }
            unsigned u = ordf(best);
            unsigned wm = __reduce_max_sync(0xffffffffu, u);
            unsigned bal = __ballot_sync(0xffffffffu, u == wm);
            int src = __ffs(bal) - 1;
            bi = __shfl_sync(0xffffffffu, bi, src);
            if (l == 0) g_lasttag[q ? b1 : b0] = bi;
        }
    }
}

// ---------------- K2: traceback + score + ll ------------------------
// One block per batch. 128 threads: load 64KB bp slab into smem + score
// gather (overlapped). Thread 0: chase backpointers (LDS.U8 chain).
__global__ __launch_bounds__(128) void k_traceback(const float* __restrict__ emis,
                                                   const int* __restrict__ tags,
                                                   const int* __restrict__ mask,
                                                   const float* __restrict__ trans,
                                                   float* __restrict__ out_ll,
                                                   float* __restrict__ out_tags) {
    extern __shared__ unsigned char sbp[];  // 64KB
    __shared__ float sred[4];
    const int b = blockIdx.x;
    const int tid = threadIdx.x;

    const float4* src = (const float4*)(g_bp + (size_t)b * TT * NN);
    #pragma unroll
    for (int i = 0; i < 32; i++)
        ((float4*)sbp)[tid + i * 128] = src[tid + i * 128];

    // sequence score (gather + block reduce)
    {
        const float* eb = emis + (size_t)b * TT * NN;
        const int* tb = tags + (size_t)b * TT;
        const int* mb = mask + (size_t)b * TT;
        float acc = 0.f;
        for (int t = tid; t < TT; t += 128) {
            int tg = tb[t];
            float mf = (float)mb[t];
            float u = eb[(size_t)t * NN + tg] * mf;
            float bi = 0.f;
            if (t > 0) {
                int tp = tb[t - 1];
                bi = trans[tp * NN + tg] * mf;
            }
            acc += u + bi;
        }
        #pragma unroll
        for (int o = 16; o; o >>= 1) acc += __shfl_xor_sync(0xffffffffu, acc, o);
        if ((tid & 31) == 0) sred[tid >> 5] = acc;
    }
    __syncthreads();

    if (tid == 0) {
        float score = sred[0] + sred[1] + sred[2] + sred[3];
        out_ll[b] = score - g_lognorm[b];

        float* ot = out_tags + (size_t)b * TT;
        int tag = g_lasttag[b];
        ot[TT - 1] = (float)tag;
        for (int t = TT - 2; t >= 0; t--) {
            tag = sbp[(t + 1) * NN + tag];
            ot[t] = (float)tag;
        }
    }
}

// ---------------- launch ---------------------------------------------
extern "C" void kernel_launch(void* const* d_in, const int* in_sizes, int n_in,
                              void* d_out, int out_size) {
    const float* emis  = (const float*)d_in[0];
    const int*   tags  = (const int*)d_in[1];
    const int*   mask  = (const int*)d_in[2];
    const float* trans = (const float*)d_in[3];
    float* out = (float*)d_out;

    float* out_ll    = out;
    float* out_trans = out + BB;
    float* out_tags  = out + BB + NN * NN;

    const int SM64 = NN * NN * (int)sizeof(float);   // 64KB
    cudaFuncSetAttribute(k_recur, cudaFuncAttributeMaxDynamicSharedMemorySize, SM64);
    cudaFuncSetAttribute(k_traceback, cudaFuncAttributeMaxDynamicSharedMemorySize, SM64);

    k_prep<<<(NN * NN + 255) / 256, 256>>>(trans, out_trans);
    k_recur<<<BB, 256, SM64>>>(emis, mask, trans);
    k_traceback<<<BB, 128, SM64>>>(emis, tags, mask, trans, out_ll, out_tags);
}

// round 12
// speedup vs baseline: 1.0012x; 1.0012x over previous
#include <cuda_runtime.h>
#include <cstdint>

// Problem constants
#define BB 256
#define TT 512
#define NN 128

// ---------------- device scratch ----------------
__device__ float g_E[NN * NN];                 // exp(trans)
__device__ float g_lognorm[BB];
__device__ unsigned char g_bp[(size_t)BB * TT * NN]; // backpointers, 16.7 MB
__device__ int   g_lasttag[BB];

__device__ __forceinline__ unsigned ordf(float f) {
    unsigned u = __float_as_uint(f);
    return u ^ (((int)u >> 31) | 0x80000000u);
}

__device__ __forceinline__ void ffma2(unsigned long long& d,
                                      unsigned long long a,
                                      unsigned long long b) {
    asm("fma.rn.f32x2 %0, %1, %2, %0;" : "+l"(d) : "l"(a), "l"(b));
}

__device__ __forceinline__ unsigned long long add2(unsigned long long a,
                                                   unsigned long long b) {
    unsigned long long d;
    asm("add.rn.f32x2 %0, %1, %2;" : "=l"(d) : "l"(a), "l"(b));
    return d;
}

__device__ __forceinline__ float lo32(unsigned long long v) {
    return __uint_as_float((unsigned)v);
}
__device__ __forceinline__ float hi32(unsigned long long v) {
    return __uint_as_float((unsigned)(v >> 32));
}

// ---------------- K0: prep -----------------------------------------
__global__ void k_prep(const float* __restrict__ trans, float* __restrict__ out_trans) {
    int idx = blockIdx.x * 256 + threadIdx.x;
    if (idx < NN * NN) {
        float v = trans[idx];
        g_E[idx] = __expf(v);
        out_trans[idx] = v;
    }
}

// ---------------- K1: fused recurrences ------------------------------
// grid = 256, 256 threads. blockIdx&1: 0 = forward, 1 = viterbi (parity
// split — empirically fastest placement, R7/R10).
// Thread (h = tid>>7, j = tid&127): candidate-half h of column j, both
// batches in the compute phase; combine phase: batch h, column j.
// 2 syncs/step; matrix half-column in 64 regs; 4 warps/SMSP at occ 2.
__global__ __launch_bounds__(256, 2) void k_recur(const float* __restrict__ emis,
                                                  const int* __restrict__ mask,
                                                  const float* __restrict__ trans) {
    extern __shared__ float transS[];   // 64KB, viterbi blocks only (row-major)

    const int tid = threadIdx.x;
    const int h = tid >> 7;
    const int j = tid & 127;
    const int type = blockIdx.x & 1;
    const int p = blockIdx.x >> 1;
    const int b0 = 2 * p;
    const int b1 = b0 + 1;

    __shared__ __align__(16) float buf[2][2][NN];   // [sel][batch][state]
    __shared__ __align__(16) float pm[2][2][NN];    // partials [batch][half][col]
    __shared__ int pidx[2][2][NN];                  // partial argmax (viterbi)
    __shared__ float csm[2][2];                     // [sel][batch] centers (fwd)
    __shared__ unsigned char vmk[2][TT];

    // this thread's combine-batch emissions
    const float* eH = emis + (size_t)(h ? b1 : b0) * TT * NN;

    for (int i = tid; i < TT; i += 256) {
        vmk[0][i] = (unsigned char)mask[(size_t)b0 * TT + i];
        vmk[1][i] = (unsigned char)mask[(size_t)b1 * TT + i];
    }

    if (type == 0) {
        // ============ forward: alpha'_j = log(sum_i p_i E_ij) + c + emit
        unsigned long long E2[32];   // E[h*64+2k..+1][j] packed
        {
            const float* Ej = g_E + (size_t)(h * 64) * NN + j;
            #pragma unroll
            for (int k = 0; k < 32; k++) {
                unsigned lo = __float_as_uint(Ej[(size_t)(2 * k) * NN]);
                unsigned hi = __float_as_uint(Ej[(size_t)(2 * k + 1) * NN]);
                E2[k] = (unsigned long long)lo | ((unsigned long long)hi << 32);
            }
        }

        float a = eH[j];
        float c = eH[0];
        buf[0][h][j] = __expf(a - c);
        if (j == 0) csm[0][h] = a;
        float en = eH[NN + j];
        int sel = 0;
        __syncthreads();

        for (int t = 1; t < TT; t++) {
            // partial dots over candidate-half h, both batches
            unsigned long long acc0[2] = {0ull, 0ull};
            unsigned long long acc1[2] = {0ull, 0ull};
            const ulonglong2* p0 = (const ulonglong2*)(buf[sel][0] + h * 64);
            const ulonglong2* p1 = (const ulonglong2*)(buf[sel][1] + h * 64);
            #pragma unroll
            for (int k = 0; k < 16; k++) {
                ulonglong2 v0 = p0[k];
                ulonglong2 v1 = p1[k];
                ffma2(acc0[0], v0.x, E2[2 * k]);
                ffma2(acc0[1], v0.y, E2[2 * k + 1]);
                ffma2(acc1[0], v1.x, E2[2 * k]);
                ffma2(acc1[1], v1.y, E2[2 * k + 1]);
            }
            pm[0][h][j] = (lo32(acc0[0]) + hi32(acc0[0])) +
                          (lo32(acc0[1]) + hi32(acc0[1]));
            pm[1][h][j] = (lo32(acc1[0]) + hi32(acc1[0])) +
                          (lo32(acc1[1]) + hi32(acc1[1]));
            __syncthreads();

            // combine for batch h
            float s = pm[h][0][j] + pm[h][1][j];
            float cn = csm[sel][h];            // alpha_{t-1}[0]
            float ec = en;
            if (t + 1 < TT) en = eH[(size_t)(t + 1) * NN + j];
            float anew = __logf(s) + c + ec;
            a = vmk[h][t] ? anew : a;
            buf[sel ^ 1][h][j] = __expf(a - cn);
            if (j == 0) csm[sel ^ 1][h] = a;
            c = cn;
            sel ^= 1;
            __syncthreads();
        }

        // publish final centers, then logsumexp per batch
        if (j == 0) csm[0][h] = c;
        __syncthreads();
        if (tid < 64) {
            int q = tid >> 5, l = tid & 31;
            float4 v = ((const float4*)buf[sel][q])[l];
            float ts = (v.x + v.y) + (v.z + v.w);
            #pragma unroll
            for (int o = 16; o; o >>= 1) ts += __shfl_xor_sync(0xffffffffu, ts, o);
            if (l == 0) g_lognorm[q ? b1 : b0] = __logf(ts) + csm[0][q];
        }
    } else {
        // ============ viterbi: alpha'_j = max_i(a_i + T_ij) + emit, w/ bp
        unsigned long long T2[32];   // T[h*64+2k..+1][j] packed
        {
            const float* Tj = trans + (size_t)(h * 64) * NN + j;
            #pragma unroll
            for (int k = 0; k < 32; k++) {
                unsigned lo = __float_as_uint(Tj[(size_t)(2 * k) * NN]);
                unsigned hi = __float_as_uint(Tj[(size_t)(2 * k + 1) * NN]);
                T2[k] = (unsigned long long)lo | ((unsigned long long)hi << 32);
            }
        }
        // row-major trans copy for the rescan
        for (int idx = tid; idx < NN * NN / 4; idx += 256)
            ((float4*)transS)[idx] = ((const float4*)trans)[idx];

        unsigned char* bpH = g_bp + (size_t)(h ? b1 : b0) * TT * NN;
        float a = eH[j];
        buf[0][h][j] = a;
        float en = eH[NN + j];
        int sel = 0;
        const float NEGINF = -3.402823466e38f;
        __syncthreads();

        for (int t = 1; t < TT; t++) {
            // tournament over candidate-half h, both batches
            #pragma unroll
            for (int q = 0; q < 2; q++) {
                float m[4] = {NEGINF, NEGINF, NEGINF, NEGINF};
                const ulonglong2* pv = (const ulonglong2*)(buf[sel][q] + h * 64);
                #pragma unroll
                for (int k = 0; k < 16; k++) {   // cands h*64+4k.., group k>>2
                    ulonglong2 v = pv[k];
                    unsigned long long w0 = add2(v.x, T2[2 * k]);
                    unsigned long long w1 = add2(v.y, T2[2 * k + 1]);
                    const int g = k >> 2;
                    m[g] = fmaxf(m[g], lo32(w0));
                    m[g] = fmaxf(m[g], hi32(w0));
                    m[g] = fmaxf(m[g], lo32(w1));
                    m[g] = fmaxf(m[g], hi32(w1));
                }
                float bm = fmaxf(fmaxf(m[0], m[1]), fmaxf(m[2], m[3]));
                int g = 3;
                #pragma unroll
                for (int qq = 2; qq >= 0; qq--) g = (m[qq] == bm) ? qq : g;
                // rescan winning group: first index attaining bm
                const int base = h * 64 + 16 * g;
                const float* al = buf[sel][q] + base;
                const float* ts = transS + (size_t)base * NN + j;
                int u = 15;
                #pragma unroll
                for (int r = 15; r >= 0; r--) {
                    float cv = al[r] + ts[(size_t)r * NN];
                    u = (cv == bm) ? r : u;
                }
                pm[q][h][j] = bm;
                pidx[q][h][j] = base + u;
            }
            __syncthreads();

            // combine for batch h (tie -> lower half = smaller index)
            float bmA = pm[h][0][j], bmB = pm[h][1][j];
            float bm = fmaxf(bmA, bmB);
            int idx = (bmA >= bmB) ? pidx[h][0][j] : pidx[h][1][j];
            float ec = en;
            if (t + 1 < TT) en = eH[(size_t)(t + 1) * NN + j];
            int mk = vmk[h][t];
            float anew = bm + ec;
            a = mk ? anew : a;
            int bidx = mk ? idx : j;
            bpH[(size_t)t * NN + j] = (unsigned char)bidx;
            buf[sel ^ 1][h][j] = a;
            sel ^= 1;
            __syncthreads();
        }

        // last_tag per batch: warp 0 -> b0, warp 1 -> b1 (first argmax)
        if (tid < 64) {
            int q = tid >> 5, l = tid & 31;
            float4 v = ((const float4*)buf[sel][q])[l];
            float best = v.x; int bi = 4 * l;
            if (v.y > best) { best = v.y; bi = 4 * l + 1; }
            if (v.z > best) { best = v.z; bi = 4 * l + 2; }
            if (v.w > best) { best = v.w; bi = 4 * l + 3; }
            unsigned u = ordf(best);
            unsigned wm = __reduce_max_sync(0xffffffffu, u);
            unsigned bal = __ballot_sync(0xffffffffu, u == wm);
            int src = __ffs(bal) - 1;
            bi = __shfl_sync(0xffffffffu, bi, src);
            if (l == 0) g_lasttag[q ? b1 : b0] = bi;
        }
    }
}

// ---------------- K2: traceback + score + ll ------------------------
// One block per batch. 128 threads: load 64KB bp slab into smem + score
// gather (overlapped). Thread 0: chase backpointers (LDS.U8 chain).
__global__ __launch_bounds__(128) void k_traceback(const float* __restrict__ emis,
                                                   const int* __restrict__ tags,
                                                   const int* __restrict__ mask,
                                                   const float* __restrict__ trans,
                                                   float* __restrict__ out_ll,
                                                   float* __restrict__ out_tags) {
    extern __shared__ unsigned char sbp[];  // 64KB
    __shared__ float sred[4];
    const int b = blockIdx.x;
    const int tid = threadIdx.x;

    const float4* src = (const float4*)(g_bp + (size_t)b * TT * NN);
    #pragma unroll
    for (int i = 0; i < 32; i++)
        ((float4*)sbp)[tid + i * 128] = src[tid + i * 128];

    // sequence score (gather + block reduce)
    {
        const float* eb = emis + (size_t)b * TT * NN;
        const int* tb = tags + (size_t)b * TT;
        const int* mb = mask + (size_t)b * TT;
        float acc = 0.f;
        for (int t = tid; t < TT; t += 128) {
            int tg = tb[t];
            float mf = (float)mb[t];
            float u = eb[(size_t)t * NN + tg] * mf;
            float bi = 0.f;
            if (t > 0) {
                int tp = tb[t - 1];
                bi = trans[tp * NN + tg] * mf;
            }
            acc += u + bi;
        }
        #pragma unroll
        for (int o = 16; o; o >>= 1) acc += __shfl_xor_sync(0xffffffffu, acc, o);
        if ((tid & 31) == 0) sred[tid >> 5] = acc;
    }
    __syncthreads();

    if (tid == 0) {
        float score = sred[0] + sred[1] + sred[2] + sred[3];
        out_ll[b] = score - g_lognorm[b];

        float* ot = out_tags + (size_t)b * TT;
        int tag = g_lasttag[b];
        ot[TT - 1] = (float)tag;
        for (int t = TT - 2; t >= 0; t--) {
            tag = sbp[(t + 1) * NN + tag];
            ot[t] = (float)tag;
        }
    }
}

// ---------------- launch ---------------------------------------------
extern "C" void kernel_launch(void* const* d_in, const int* in_sizes, int n_in,
                              void* d_out, int out_size) {
    const float* emis  = (const float*)d_in[0];
    const int*   tags  = (const int*)d_in[1];
    const int*   mask  = (const int*)d_in[2];
    const float* trans = (const float*)d_in[3];
    float* out = (float*)d_out;

    float* out_ll    = out;
    float* out_trans = out + BB;
    float* out_tags  = out + BB + NN * NN;

    const int SM64 = NN * NN * (int)sizeof(float);   // 64KB
    cudaFuncSetAttribute(k_recur, cudaFuncAttributeMaxDynamicSharedMemorySize, SM64);
    cudaFuncSetAttribute(k_traceback, cudaFuncAttributeMaxDynamicSharedMemorySize, SM64);

    k_prep<<<(NN * NN + 255) / 256, 256>>>(trans, out_trans);
    k_recur<<<BB, 256, SM64>>>(emis, mask, trans);
    k_traceback<<<BB, 128, SM64>>>(emis, tags, mask, trans, out_ll, out_tags);
}

// round 13
// speedup vs baseline: 1.1490x; 1.1476x over previous
#include <cuda_runtime.h>
#include <cstdint>

// Problem constants
#define BB 256
#define TT 512
#define NN 128

// ---------------- device scratch ----------------
__device__ float g_E[NN * NN];                 // exp(trans)
__device__ float g_lognorm[BB];
__device__ unsigned char g_bp[(size_t)BB * TT * NN]; // backpointers, 16.7 MB
__device__ int   g_lasttag[BB];

__device__ __forceinline__ unsigned ordf(float f) {
    unsigned u = __float_as_uint(f);
    return u ^ (((int)u >> 31) | 0x80000000u);
}

__device__ __forceinline__ void ffma2(unsigned long long& d,
                                      unsigned long long a,
                                      unsigned long long b) {
    asm("fma.rn.f32x2 %0, %1, %2, %0;" : "+l"(d) : "l"(a), "l"(b));
}

__device__ __forceinline__ unsigned long long add2(unsigned long long a,
                                                   unsigned long long b) {
    unsigned long long d;
    asm("add.rn.f32x2 %0, %1, %2;" : "=l"(d) : "l"(a), "l"(b));
    return d;
}

__device__ __forceinline__ float lo32(unsigned long long v) {
    return __uint_as_float((unsigned)v);
}
__device__ __forceinline__ float hi32(unsigned long long v) {
    return __uint_as_float((unsigned)(v >> 32));
}

// ---------------- K0: prep -----------------------------------------
__global__ void k_prep(const float* __restrict__ trans, float* __restrict__ out_trans) {
    int idx = blockIdx.x * 256 + threadIdx.x;
    if (idx < NN * NN) {
        float v = trans[idx];
        g_E[idx] = __expf(v);
        out_trans[idx] = v;
    }
}

// ---------------- K1a: forward (log-norm), 2 batches per block -------
// grid = 128 (= BB/2) -> one block per SM, 1 warp/SMSP.
__global__ __launch_bounds__(128, 1) void k_fwd(const float* __restrict__ emis,
                                                const int* __restrict__ mask) {
    const int p = blockIdx.x;
    const int b0 = 2 * p;
    const int b1 = b0 + 1;
    const int j = threadIdx.x;

    __shared__ __align__(16) float buf[2][2][NN];   // [sel][batch][state]
    __shared__ float csm[2][2];
    __shared__ int smask[2][TT];

    const float* e0 = emis + (size_t)b0 * TT * NN;
    const float* e1 = emis + (size_t)b1 * TT * NN;

    for (int i = j; i < TT; i += NN) {
        smask[0][i] = mask[(size_t)b0 * TT + i];
        smask[1][i] = mask[(size_t)b1 * TT + i];
    }

    unsigned long long E2[64];
    {
        const float* Ej = g_E + j;
        #pragma unroll
        for (int k = 0; k < 64; k++) {
            unsigned lo = __float_as_uint(Ej[(size_t)(2 * k) * NN]);
            unsigned hi = __float_as_uint(Ej[(size_t)(2 * k + 1) * NN]);
            E2[k] = (unsigned long long)lo | ((unsigned long long)hi << 32);
        }
    }

    float a0 = e0[j],  a1 = e1[j];
    float c0 = e0[0],  c1 = e1[0];
    float en0 = e0[NN + j], en1 = e1[NN + j];
    int sel = 0;
    __syncthreads();             // smask ready

    for (int t = 1; t < TT; t++) {
        buf[sel][0][j] = __expf(a0 - c0);
        buf[sel][1][j] = __expf(a1 - c1);
        if (j == 0) { csm[sel][0] = a0; csm[sel][1] = a1; }
        __syncthreads();
        float c0n = csm[sel][0], c1n = csm[sel][1];

        unsigned long long acc0[4] = {0ull, 0ull, 0ull, 0ull};
        unsigned long long acc1[4] = {0ull, 0ull, 0ull, 0ull};
        const ulonglong2* p0 = (const ulonglong2*)buf[sel][0];
        const ulonglong2* p1 = (const ulonglong2*)buf[sel][1];
        #pragma unroll
        for (int k = 0; k < 32; k++) {
            ulonglong2 v0 = p0[k];
            ulonglong2 v1 = p1[k];
            ffma2(acc0[(2 * k) & 3], v0.x, E2[2 * k]);
            ffma2(acc0[(2 * k + 1) & 3], v0.y, E2[2 * k + 1]);
            ffma2(acc1[(2 * k) & 3], v1.x, E2[2 * k]);
            ffma2(acc1[(2 * k + 1) & 3], v1.y, E2[2 * k + 1]);
        }
        float s0 = 0.f, s1 = 0.f;
        #pragma unroll
        for (int q = 0; q < 4; q++) {
            s0 += lo32(acc0[q]) + hi32(acc0[q]);
            s1 += lo32(acc1[q]) + hi32(acc1[q]);
        }

        float ec0 = en0, ec1 = en1;
        if (t + 1 < TT) {
            en0 = e0[(size_t)(t + 1) * NN + j];
            en1 = e1[(size_t)(t + 1) * NN + j];
        }

        float n0 = __logf(s0) + c0 + ec0;
        float n1 = __logf(s1) + c1 + ec1;
        a0 = smask[0][t] ? n0 : a0;
        a1 = smask[1][t] ? n1 : a1;
        c0 = c0n; c1 = c1n;
        sel ^= 1;
    }

    // final logsumexp, one warp per batch
    buf[0][0][j] = __expf(a0 - c0);
    buf[0][1][j] = __expf(a1 - c1);
    __syncthreads();
    const int wid = j >> 5;
    if (wid < 2) {
        const int l = j & 31;
        float4 v = ((const float4*)buf[0][wid])[l];
        float ts = (v.x + v.y) + (v.z + v.w);
        #pragma unroll
        for (int o = 16; o; o >>= 1) ts += __shfl_xor_sync(0xffffffffu, ts, o);
        if (l == 0) {
            int b = wid ? b1 : b0;
            float c = wid ? c1 : c0;
            g_lognorm[b] = __logf(ts) + c;
        }
    }
}

// ---------------- K1b: viterbi, 2 batches per block ------------------
// grid = 128 -> one block per SM. Group maxima + first-group rescan for
// the exact first-index argmax (backpointers).
__global__ __launch_bounds__(128, 1) void k_vit(const float* __restrict__ emis,
                                                const int* __restrict__ mask,
                                                const float* __restrict__ trans) {
    extern __shared__ float transS[];   // 64KB row-major trans

    const int p = blockIdx.x;
    const int b0 = 2 * p;
    const int b1 = b0 + 1;
    const int j = threadIdx.x;

    __shared__ __align__(16) float buf[2][2][NN];   // [sel][batch][state]
    __shared__ int smask[2][TT];

    const float* e0 = emis + (size_t)b0 * TT * NN;
    const float* e1 = emis + (size_t)b1 * TT * NN;

    for (int i = j; i < TT; i += NN) {
        smask[0][i] = mask[(size_t)b0 * TT + i];
        smask[1][i] = mask[(size_t)b1 * TT + i];
    }

    unsigned long long T2[64];
    {
        const float* Tj = trans + j;
        #pragma unroll
        for (int k = 0; k < 64; k++) {
            unsigned lo = __float_as_uint(Tj[(size_t)(2 * k) * NN]);
            unsigned hi = __float_as_uint(Tj[(size_t)(2 * k + 1) * NN]);
            T2[k] = (unsigned long long)lo | ((unsigned long long)hi << 32);
        }
    }
    // row-major trans copy in smem for the rescan
    for (int idx = j; idx < NN * NN / 4; idx += NN)
        ((float4*)transS)[idx] = ((const float4*)trans)[idx];

    unsigned char* bp0 = g_bp + (size_t)b0 * TT * NN;
    unsigned char* bp1 = g_bp + (size_t)b1 * TT * NN;
    float a0 = e0[j], a1 = e1[j];
    buf[0][0][j] = a0;
    buf[0][1][j] = a1;
    float en0 = e0[NN + j], en1 = e1[NN + j];
    int sel = 0;
    const float NEGINF = -3.402823466e38f;
    __syncthreads();             // buf[0] + smask + transS ready

    for (int t = 1; t < TT; t++) {
        float m0[8], m1[8];
        #pragma unroll
        for (int q = 0; q < 8; q++) { m0[q] = NEGINF; m1[q] = NEGINF; }
        const ulonglong2* p0 = (const ulonglong2*)buf[sel][0];
        const ulonglong2* p1 = (const ulonglong2*)buf[sel][1];
        #pragma unroll
        for (int k = 0; k < 32; k++) {           // cands 4k..4k+3, group k>>2
            ulonglong2 v0 = p0[k];
            ulonglong2 v1 = p1[k];
            unsigned long long w00 = add2(v0.x, T2[2 * k]);
            unsigned long long w01 = add2(v0.y, T2[2 * k + 1]);
            unsigned long long w10 = add2(v1.x, T2[2 * k]);
            unsigned long long w11 = add2(v1.y, T2[2 * k + 1]);
            const int q = k >> 2;
            m0[q] = fmaxf(m0[q], lo32(w00));
            m0[q] = fmaxf(m0[q], hi32(w00));
            m0[q] = fmaxf(m0[q], lo32(w01));
            m0[q] = fmaxf(m0[q], hi32(w01));
            m1[q] = fmaxf(m1[q], lo32(w10));
            m1[q] = fmaxf(m1[q], hi32(w10));
            m1[q] = fmaxf(m1[q], lo32(w11));
            m1[q] = fmaxf(m1[q], hi32(w11));
        }
        float bm0 = fmaxf(fmaxf(fmaxf(m0[0], m0[1]), fmaxf(m0[2], m0[3])),
                          fmaxf(fmaxf(m0[4], m0[5]), fmaxf(m0[6], m0[7])));
        float bm1 = fmaxf(fmaxf(fmaxf(m1[0], m1[1]), fmaxf(m1[2], m1[3])),
                          fmaxf(fmaxf(m1[4], m1[5]), fmaxf(m1[6], m1[7])));

        // first group attaining the max
        int g0 = 7, g1 = 7;
        #pragma unroll
        for (int q = 6; q >= 0; q--) {
            g0 = (m0[q] == bm0) ? q : g0;
            g1 = (m1[q] == bm1) ? q : g1;
        }

        // rescan winning group: first index with candidate == bm
        int u0 = 15, u1 = 15;
        {
            const float* al0 = buf[sel][0] + 16 * g0;
            const float* al1 = buf[sel][1] + 16 * g1;
            float av0[16], av1[16];
            #pragma unroll
            for (int r = 0; r < 4; r++) {
                float4 x0 = ((const float4*)al0)[r];
                float4 x1 = ((const float4*)al1)[r];
                av0[4 * r] = x0.x; av0[4 * r + 1] = x0.y;
                av0[4 * r + 2] = x0.z; av0[4 * r + 3] = x0.w;
                av1[4 * r] = x1.x; av1[4 * r + 1] = x1.y;
                av1[4 * r + 2] = x1.z; av1[4 * r + 3] = x1.w;
            }
            const float* ts0 = transS + (size_t)(16 * g0) * NN + j;
            const float* ts1 = transS + (size_t)(16 * g1) * NN + j;
            #pragma unroll
            for (int r = 15; r >= 0; r--) {
                float c0v = av0[r] + ts0[(size_t)r * NN];
                float c1v = av1[r] + ts1[(size_t)r * NN];
                u0 = (c0v == bm0) ? r : u0;
                u1 = (c1v == bm1) ? r : u1;
            }
        }

        float ec0 = en0, ec1 = en1;
        if (t + 1 < TT) {
            en0 = e0[(size_t)(t + 1) * NN + j];
            en1 = e1[(size_t)(t + 1) * NN + j];
        }

        int msk0 = smask[0][t], msk1 = smask[1][t];
        float n0 = bm0 + ec0;
        float n1 = bm1 + ec1;
        a0 = msk0 ? n0 : a0;
        a1 = msk1 ? n1 : a1;
        int v0i = msk0 ? (16 * g0 + u0) : j;
        int v1i = msk1 ? (16 * g1 + u1) : j;
        bp0[(size_t)t * NN + j] = (unsigned char)v0i;
        bp1[(size_t)t * NN + j] = (unsigned char)v1i;
        buf[sel ^ 1][0][j] = a0;
        buf[sel ^ 1][1][j] = a1;
        sel ^= 1;
        __syncthreads();
    }

    // last_tag per batch: one warp each (first-index argmax)
    const int wid = j >> 5;
    if (wid < 2) {
        const int l = j & 31;
        float4 v = ((const float4*)buf[sel][wid])[l];
        float best = v.x; int bi = 4 * l;
        if (v.y > best) { best = v.y; bi = 4 * l + 1; }
        if (v.z > best) { best = v.z; bi = 4 * l + 2; }
        if (v.w > best) { best = v.w; bi = 4 * l + 3; }
        unsigned u = ordf(best);
        unsigned wm = __reduce_max_sync(0xffffffffu, u);
        unsigned bal = __ballot_sync(0xffffffffu, u == wm);
        int src = __ffs(bal) - 1;
        bi = __shfl_sync(0xffffffffu, bi, src);
        if (l == 0) g_lasttag[wid ? b1 : b0] = bi;
    }
}

// ---------------- K2: traceback + score + ll ------------------------
// One block per batch. All 128 threads: load 64KB bp slab into smem and
// compute the sequence score (gather overlaps slab load). Thread 0: chase.
__global__ __launch_bounds__(128) void k_traceback(const float* __restrict__ emis,
                                                   const int* __restrict__ tags,
                                                   const int* __restrict__ mask,
                                                   const float* __restrict__ trans,
                                                   float* __restrict__ out_ll,
                                                   float* __restrict__ out_tags) {
    extern __shared__ unsigned char sbp[];  // 64KB
    __shared__ float sred[4];
    const int b = blockIdx.x;
    const int tid = threadIdx.x;

    const float4* src = (const float4*)(g_bp + (size_t)b * TT * NN);
    #pragma unroll
    for (int i = 0; i < 32; i++)
        ((float4*)sbp)[tid + i * 128] = src[tid + i * 128];

    // sequence score (gather + block reduce)
    {
        const float* eb = emis + (size_t)b * TT * NN;
        const int* tb = tags + (size_t)b * TT;
        const int* mb = mask + (size_t)b * TT;
        float acc = 0.f;
        for (int t = tid; t < TT; t += 128) {
            int tg = tb[t];
            float mf = (float)mb[t];
            float u = eb[(size_t)t * NN + tg] * mf;
            float bi = 0.f;
            if (t > 0) {
                int tp = tb[t - 1];
                bi = trans[tp * NN + tg] * mf;
            }
            acc += u + bi;
        }
        #pragma unroll
        for (int o = 16; o; o >>= 1) acc += __shfl_xor_sync(0xffffffffu, acc, o);
        if ((tid & 31) == 0) sred[tid >> 5] = acc;
    }
    __syncthreads();

    if (tid == 0) {
        float score = sred[0] + sred[1] + sred[2] + sred[3];
        out_ll[b] = score - g_lognorm[b];

        float* ot = out_tags + (size_t)b * TT;
        int tag = g_lasttag[b];
        ot[TT - 1] = (float)tag;
        for (int t = TT - 2; t >= 0; t--) {
            tag = sbp[(t + 1) * NN + tag];
            ot[t] = (float)tag;
        }
    }
}

// ---------------- launch ---------------------------------------------
extern "C" void kernel_launch(void* const* d_in, const int* in_sizes, int n_in,
                              void* d_out, int out_size) {
    const float* emis  = (const float*)d_in[0];
    const int*   tags  = (const int*)d_in[1];
    const int*   mask  = (const int*)d_in[2];
    const float* trans = (const float*)d_in[3];
    float* out = (float*)d_out;

    float* out_ll    = out;
    float* out_trans = out + BB;
    float* out_tags  = out + BB + NN * NN;

    const int SM64 = NN * NN * (int)sizeof(float);   // 64KB
    cudaFuncSetAttribute(k_vit, cudaFuncAttributeMaxDynamicSharedMemorySize, SM64);
    cudaFuncSetAttribute(k_traceback, cudaFuncAttributeMaxDynamicSharedMemorySize, SM64);

    k_prep<<<(NN * NN + 255) / 256, 256>>>(trans, out_trans);
    k_vit<<<BB / 2, 128, SM64>>>(emis, mask, trans);
    k_fwd<<<BB / 2, 128>>>(emis, mask);
    k_traceback<<<BB, 128, SM64>>>(emis, tags, mask, trans, out_ll, out_tags);
}